// round 4
// baseline (speedup 1.0000x reference)
#include <cuda_runtime.h>

#define BB 64
#define CC 64
#define HH 128
#define WW 128

// Scratch (allocation-free rule: __device__ globals)
__device__ float g_cs_e [BB * CC * WW];   // colsum_e [b,c,w]  = sum_h exp(x-m)
__device__ float g_cs_ey[BB * CC * WW];   // colsum_ey[b,c,w]  = sum_h exp(x-m)*wy[h]

// ---------------------------------------------------------------------------
// Pass 1: one CTA per (b,c) slab (128x128 f32 = 64KB).
//   512 threads = 16 warps (h-subgroups) x 32 lanes (w-groups of 4).
//   Each warp is fully independent until the final combine: it loads its 8
//   rows, takes its own max (shfl, no barrier), exps against the WARP max and
//   accumulates. The single __syncthreads is at the combine, where reducers
//   rescale each warp's partials by exp(m_warp - m_cta). This keeps the
//   memory pipe busy (no CTA-wide load barrier before compute).
// ---------------------------------------------------------------------------
__global__ __launch_bounds__(512, 2)
void sam_pass1(const float* __restrict__ x) {
    const int bc  = blockIdx.x;                 // 0..4095
    const int tid = threadIdx.x;
    const int wg  = tid & 31;                   // w-group (4 floats)
    const int hs  = tid >> 5;                   // warp id == h subgroup 0..15

    const float4* xp = reinterpret_cast<const float4*>(x)
                     + (size_t)bc * (HH * WW / 4);

    float4 v[8];
#pragma unroll
    for (int r = 0; r < 8; r++)
        v[r] = __ldcs(&xp[(hs + 16 * r) * (WW / 4) + wg]);

    // ---- warp-local max (no barrier) ----
    float m = v[0].x;
#pragma unroll
    for (int r = 0; r < 8; r++)
        m = fmaxf(m, fmaxf(fmaxf(v[r].x, v[r].y), fmaxf(v[r].z, v[r].w)));
#pragma unroll
    for (int o = 16; o; o >>= 1)
        m = fmaxf(m, __shfl_xor_sync(0xffffffffu, m, o));
    // m == warp max; all values in this warp satisfy x - m <= 0

    // ---- exp against warp max + per-thread column partial sums ----
    const float inv127 = 1.0f / 127.0f;
    float ae0 = 0.f, ae1 = 0.f, ae2 = 0.f, ae3 = 0.f;
    float ay0 = 0.f, ay1 = 0.f, ay2 = 0.f, ay3 = 0.f;
#pragma unroll
    for (int r = 0; r < 8; r++) {
        const float wy = (float)(hs + 16 * r) * inv127;
        float e0 = __expf(v[r].x - m);
        float e1 = __expf(v[r].y - m);
        float e2 = __expf(v[r].z - m);
        float e3 = __expf(v[r].w - m);
        ae0 += e0; ay0 += e0 * wy;
        ae1 += e1; ay1 += e1 * wy;
        ae2 += e2; ay2 += e2 * wy;
        ae3 += e3; ay3 += e3 * wy;
    }

    // ---- combine: rescale each warp's partials to the CTA max ----
    __shared__ float4 se[16][32];   // [warp][wg] -> flat [16][128]
    __shared__ float4 sy[16][32];
    __shared__ float  smax[16];
    se[hs][wg] = make_float4(ae0, ae1, ae2, ae3);
    sy[hs][wg] = make_float4(ay0, ay1, ay2, ay3);
    if (wg == 0) smax[hs] = m;
    __syncthreads();

    if (tid < 256) {
        float mc = smax[0];
#pragma unroll
        for (int k = 1; k < 16; k++) mc = fmaxf(mc, smax[k]);

        if (tid < 128) {
            const float* p = reinterpret_cast<const float*>(se);
            float s = 0.f;
#pragma unroll
            for (int k = 0; k < 16; k++)
                s += p[k * 128 + tid] * __expf(smax[k] - mc);
            g_cs_e[(size_t)bc * WW + tid] = s;
        } else {
            const int w = tid - 128;
            const float* p = reinterpret_cast<const float*>(sy);
            float s = 0.f;
#pragma unroll
            for (int k = 0; k < 16; k++)
                s += p[k * 128 + w] * __expf(smax[k] - mc);
            g_cs_ey[(size_t)bc * WW + w] = s;
        }
    }
}

// ---------------------------------------------------------------------------
// Pass 2: one CTA per batch b, 1024 threads.
//   ALL global loads (phase-A column sums AND phase-B channel data) are
//   issued up front into registers, so the rs barrier gates only smem math.
// ---------------------------------------------------------------------------
__global__ __launch_bounds__(1024)
void sam_pass2(float* __restrict__ out) {
    const int b   = blockIdx.x;                 // 0..63
    const int tid = threadIdx.x;

    const float* __restrict__ cse = g_cs_e  + (size_t)b * CC * WW;
    const float* __restrict__ csy = g_cs_ey + (size_t)b * CC * WW;

    __shared__ float sA[8][WW];
    __shared__ float rs[WW];

    // Phase A loads (for the sum over c)
    const int w  = tid & 127;
    const int cg = tid >> 7;                    // 0..7
    float a[8];
#pragma unroll
    for (int k = 0; k < 8; k++)
        a[k] = cse[(cg + 8 * k) * WW + w];

    // Phase B prefetch (channel dot-product data), independent of rs
    const int warp = tid >> 5;                  // 0..31
    const int lane = tid & 31;
    float pe[2][4], py[2][4];
#pragma unroll
    for (int i = 0; i < 2; i++) {
        const int c = warp * 2 + i;
#pragma unroll
        for (int j = 0; j < 4; j++) {
            const int ww = lane + 32 * j;
            pe[i][j] = cse[c * WW + ww];
            py[i][j] = csy[c * WW + ww];
        }
    }

    // Phase A reduce
    {
        float s = 0.f;
#pragma unroll
        for (int k = 0; k < 8; k++) s += a[k];
        sA[cg][w] = s;
    }
    __syncthreads();
    if (tid < WW) {
        float s = 0.f;
#pragma unroll
        for (int k = 0; k < 8; k++) s += sA[k][tid];
        rs[tid] = 1.0f / s;
    }
    __syncthreads();

    // Phase B: per-channel dot products (data already in registers)
    const float inv127 = 1.0f / 127.0f;
#pragma unroll
    for (int i = 0; i < 2; i++) {
        const int c = warp * 2 + i;
        float xx = 0.f, xy = 0.f;
#pragma unroll
        for (int j = 0; j < 4; j++) {
            const int ww = lane + 32 * j;
            const float r = rs[ww];
            xx += pe[i][j] * ((float)ww * inv127) * r;
            xy += py[i][j] * r;
        }
#pragma unroll
        for (int o = 16; o; o >>= 1) {
            xx += __shfl_xor_sync(0xffffffffu, xx, o);
            xy += __shfl_xor_sync(0xffffffffu, xy, o);
        }
        if (lane == 0) {
            out[((size_t)b * CC + c) * 2 + 0] = xx;
            out[((size_t)b * CC + c) * 2 + 1] = xy;
        }
    }
}

extern "C" void kernel_launch(void* const* d_in, const int* in_sizes, int n_in,
                              void* d_out, int out_size) {
    const float* x = (const float*)d_in[0];
    float* out = (float*)d_out;
    sam_pass1<<<BB * CC, 512>>>(x);
    sam_pass2<<<BB, 1024>>>(out);
}

// round 5
// speedup vs baseline: 1.1094x; 1.1094x over previous
#include <cuda_runtime.h>

#define BB 64
#define CC 64
#define HH 128
#define WW 128
#define NSLAB (BB * CC)
#define GRID1 296   // 2 CTAs/SM on 148 SMs, <=2/SM on 152; single wave, persistent

// Scratch (allocation-free rule: __device__ globals)
__device__ float g_cs_e [BB * CC * WW];   // colsum_e [b,c,w]  = sum_h exp(x-m)
__device__ float g_cs_ey[BB * CC * WW];   // colsum_ey[b,c,w]  = sum_h exp(x-m)*wy[h]

// ---------------------------------------------------------------------------
// Pass 1 (persistent): grid-stride over 4096 (b,c) slabs, 512 threads/CTA,
// 2 CTAs/SM. Each slab (128x128 f32 = 64KB) is register-staged:
//   16 warps x 32 lanes; warp hs owns rows {hs + 16r}, each thread 8 float4.
// Exact CTA max (matches reference), then exp + column accumulation.
// The NEXT slab's loads are issued before the combine barriers so DRAM
// traffic continues through barrier + smem epilogue (no inter-slab drain,
// no wave transitions).
// ---------------------------------------------------------------------------
__global__ __launch_bounds__(512, 2)
void sam_pass1(const float* __restrict__ x) {
    const int tid = threadIdx.x;
    const int wg  = tid & 31;                   // w-group (4 consecutive floats)
    const int hs  = tid >> 5;                   // warp id == h subgroup 0..15

    __shared__ float  smax[16];
    __shared__ float4 se[16][32];               // [warp][wg] -> flat [16][128]
    __shared__ float4 sy[16][32];

    const float4* __restrict__ xp = reinterpret_cast<const float4*>(x);
    const float inv127 = 1.0f / 127.0f;

    int bc = blockIdx.x;
    float4 v[8];
    if (bc < NSLAB) {
        const float4* p = xp + (size_t)bc * (HH * WW / 4);
#pragma unroll
        for (int r = 0; r < 8; r++)
            v[r] = p[(hs + 16 * r) * (WW / 4) + wg];
    }

    for (; bc < NSLAB; bc += GRID1) {
        // ---- warp max, then CTA max ----
        float m = v[0].x;
#pragma unroll
        for (int r = 0; r < 8; r++)
            m = fmaxf(m, fmaxf(fmaxf(v[r].x, v[r].y), fmaxf(v[r].z, v[r].w)));
#pragma unroll
        for (int o = 16; o; o >>= 1)
            m = fmaxf(m, __shfl_xor_sync(0xffffffffu, m, o));
        if (wg == 0) smax[hs] = m;
        __syncthreads();                        // barrier A (also fences se/sy reuse)
        float mc = smax[0];
#pragma unroll
        for (int k = 1; k < 16; k++) mc = fmaxf(mc, smax[k]);

        // ---- exp + per-thread column partial sums (consumes v) ----
        float ae0 = 0.f, ae1 = 0.f, ae2 = 0.f, ae3 = 0.f;
        float ay0 = 0.f, ay1 = 0.f, ay2 = 0.f, ay3 = 0.f;
#pragma unroll
        for (int r = 0; r < 8; r++) {
            const float wy = (float)(hs + 16 * r) * inv127;
            float e0 = __expf(v[r].x - mc);
            float e1 = __expf(v[r].y - mc);
            float e2 = __expf(v[r].z - mc);
            float e3 = __expf(v[r].w - mc);
            ae0 += e0; ay0 += e0 * wy;
            ae1 += e1; ay1 += e1 * wy;
            ae2 += e2; ay2 += e2 * wy;
            ae3 += e3; ay3 += e3 * wy;
        }

        // ---- prefetch next slab (overlaps barriers + epilogue below) ----
        const int nbc = bc + GRID1;
        if (nbc < NSLAB) {
            const float4* p = xp + (size_t)nbc * (HH * WW / 4);
#pragma unroll
            for (int r = 0; r < 8; r++)
                v[r] = p[(hs + 16 * r) * (WW / 4) + wg];
        }

        // ---- deterministic combine over 16 warps ----
        se[hs][wg] = make_float4(ae0, ae1, ae2, ae3);
        sy[hs][wg] = make_float4(ay0, ay1, ay2, ay3);
        __syncthreads();                        // barrier B

        if (tid < 128) {
            const float* p = reinterpret_cast<const float*>(se);
            float s = 0.f;
#pragma unroll
            for (int k = 0; k < 16; k++) s += p[k * 128 + tid];
            g_cs_e[(size_t)bc * WW + tid] = s;
        } else if (tid < 256) {
            const int w = tid - 128;
            const float* p = reinterpret_cast<const float*>(sy);
            float s = 0.f;
#pragma unroll
            for (int k = 0; k < 16; k++) s += p[k * 128 + w];
            g_cs_ey[(size_t)bc * WW + w] = s;
        }
    }
}

// ---------------------------------------------------------------------------
// Pass 2: 2 CTAs per batch (grid=128), 512 threads. Each CTA redundantly
// computes rs[b,w] = 1 / sum_c colsum_e (L2-hot), then handles 32 channels.
// All global loads are issued up front so the barrier gates only smem math.
// ---------------------------------------------------------------------------
__global__ __launch_bounds__(512)
void sam_pass2(float* __restrict__ out) {
    const int b    = blockIdx.x >> 1;
    const int half = blockIdx.x & 1;
    const int tid  = threadIdx.x;

    const float* __restrict__ cse = g_cs_e  + (size_t)b * CC * WW;
    const float* __restrict__ csy = g_cs_ey + (size_t)b * CC * WW;

    __shared__ float sA[4][WW];
    __shared__ float rs[WW];

    // Loads for rs (sum over all 64 channels, 4 c-groups x 16)
    const int w  = tid & 127;
    const int cg = tid >> 7;                    // 0..3
    float a[16];
#pragma unroll
    for (int k = 0; k < 16; k++)
        a[k] = cse[(cg + 4 * k) * WW + w];

    // Prefetch phase-B channel data (this CTA's 32 channels)
    const int warp = tid >> 5;                  // 0..15
    const int lane = tid & 31;
    float pe[2][4], py[2][4];
#pragma unroll
    for (int i = 0; i < 2; i++) {
        const int c = half * 32 + warp * 2 + i;
#pragma unroll
        for (int j = 0; j < 4; j++) {
            const int ww = lane + 32 * j;
            pe[i][j] = cse[c * WW + ww];
            py[i][j] = csy[c * WW + ww];
        }
    }

    // rs reduce
    {
        float s = 0.f;
#pragma unroll
        for (int k = 0; k < 16; k++) s += a[k];
        sA[cg][w] = s;
    }
    __syncthreads();
    if (tid < WW) {
        rs[tid] = 1.0f / (sA[0][tid] + sA[1][tid] + sA[2][tid] + sA[3][tid]);
    }
    __syncthreads();

    // Phase B: per-channel dot products (data already in registers)
    const float inv127 = 1.0f / 127.0f;
#pragma unroll
    for (int i = 0; i < 2; i++) {
        const int c = half * 32 + warp * 2 + i;
        float xx = 0.f, xy = 0.f;
#pragma unroll
        for (int j = 0; j < 4; j++) {
            const int ww = lane + 32 * j;
            const float r = rs[ww];
            xx += pe[i][j] * ((float)ww * inv127) * r;
            xy += py[i][j] * r;
        }
#pragma unroll
        for (int o = 16; o; o >>= 1) {
            xx += __shfl_xor_sync(0xffffffffu, xx, o);
            xy += __shfl_xor_sync(0xffffffffu, xy, o);
        }
        if (lane == 0) {
            out[((size_t)b * CC + c) * 2 + 0] = xx;
            out[((size_t)b * CC + c) * 2 + 1] = xy;
        }
    }
}

extern "C" void kernel_launch(void* const* d_in, const int* in_sizes, int n_in,
                              void* d_out, int out_size) {
    const float* x = (const float*)d_in[0];
    float* out = (float*)d_out;
    sam_pass1<<<GRID1, 512>>>(x);
    sam_pass2<<<2 * BB, 512>>>(out);
}